// round 2
// baseline (speedup 1.0000x reference)
#include <cuda_runtime.h>

#define H 1024
#define B 8
#define T 4096

// Scratch: v[b][i] = sum_j W[i][j] * context[b][j]
__device__ float g_v[B * H];

// Kernel 1: 128 blocks x 256 threads. ctx staged in smem once per block.
// Each warp owns one W row; the 8 W float4 loads are front-batched (8-deep MLP),
// then the 8-batch dot products run against shared-memory ctx only.
__global__ void __launch_bounds__(256) compute_v_kernel(
    const float* __restrict__ W,     // (H, H)
    const float* __restrict__ ctx)   // (B, H)
{
    __shared__ float sctx[B * H];    // 32 KB
    for (int idx = threadIdx.x; idx < B * H; idx += 256)
        sctx[idx] = ctx[idx];
    __syncthreads();

    const int warp = threadIdx.x >> 5;
    const int lane = threadIdx.x & 31;
    const int i = blockIdx.x * 8 + warp;          // W row, 128 blocks * 8 warps = 1024

    const float4* wr = reinterpret_cast<const float4*>(W + (size_t)i * H);
    float4 w[8];
#pragma unroll
    for (int k = 0; k < 8; k++)                   // front-batched global loads
        w[k] = wr[lane + 32 * k];

#pragma unroll
    for (int b = 0; b < B; b++) {
        const float4* c4 = reinterpret_cast<const float4*>(sctx + b * H);
        float acc = 0.0f;
#pragma unroll
        for (int k = 0; k < 8; k++) {
            const float4 c = c4[lane + 32 * k];
            acc += w[k].x * c.x + w[k].y * c.y + w[k].z * c.z + w[k].w * c.w;
        }
#pragma unroll
        for (int o = 16; o; o >>= 1) acc += __shfl_xor_sync(0xFFFFFFFFu, acc, o);
        if (lane == 0) g_v[b * H + i] = acc;
    }
}

// Kernel 2: persistent. 888 blocks = 148 SMs x 6 resident blocks. Each block
// stages ALL 8 v vectors (32 KB) once, then grid-strides over the 32768 rows.
// One warp per row per pass: 8 front-batched LDG.128 + smem dot + shuffle reduce.
#define SCORE_BLOCKS (148 * 6)

__global__ void __launch_bounds__(256, 6) score_kernel(
    const float* __restrict__ states,  // (B, T, H)
    const float* __restrict__ bias,    // (1,)
    float* __restrict__ out)           // (B*T,)
{
    __shared__ float sv[B * H];        // 32 KB
    for (int idx = threadIdx.x; idx < B * H; idx += 256)
        sv[idx] = g_v[idx];
    __syncthreads();

    const float bb = bias[0];
    const int lane = threadIdx.x & 31;
    const int warp_gid = blockIdx.x * 8 + (threadIdx.x >> 5);
    const int nwarps = SCORE_BLOCKS * 8;

    for (int row = warp_gid; row < B * T; row += nwarps) {
        const float4* s4 = reinterpret_cast<const float4*>(states + (size_t)row * H);
        const float4* v4 = reinterpret_cast<const float4*>(sv + ((row >> 12) << 10)); // (row/T)*H

        float acc = 0.0f;
#pragma unroll
        for (int k = 0; k < 8; k++) {
            const float4 x = s4[lane + 32 * k];
            const float4 w = v4[lane + 32 * k];
            acc += x.x * w.x + x.y * w.y + x.z * w.z + x.w * w.w;
        }
#pragma unroll
        for (int o = 16; o; o >>= 1) acc += __shfl_xor_sync(0xFFFFFFFFu, acc, o);
        if (lane == 0) out[row] = acc + bb;
    }
}

extern "C" void kernel_launch(void* const* d_in, const int* in_sizes, int n_in,
                              void* d_out, int out_size)
{
    const float* states = (const float*)d_in[0];   // (B, T, H)
    const float* ctx    = (const float*)d_in[1];   // (B, H)
    const float* W      = (const float*)d_in[2];   // (1, H, H)
    const float* bias   = (const float*)d_in[3];   // (1,)
    float* out = (float*)d_out;                    // (B, T, 1)

    compute_v_kernel<<<H / 8, 256>>>(W, ctx);
    score_kernel<<<SCORE_BLOCKS, 256>>>(states, bias, out);
}

// round 3
// speedup vs baseline: 1.1089x; 1.1089x over previous
#include <cuda_runtime.h>

#define H 1024
#define B 8
#define T 4096

// Scratch: v[b][i] = sum_j W[i][j] * context[b][j]
__device__ float g_v[B * H];

// Kernel 1: 128 blocks x 256 threads. ctx staged in smem once per block.
// Each warp owns one W row; 8 front-batched LDG.128 of W, then 8-batch dot
// products against shared-memory ctx.
__global__ void __launch_bounds__(256) compute_v_kernel(
    const float* __restrict__ W,     // (H, H)
    const float* __restrict__ ctx)   // (B, H)
{
    __shared__ float sctx[B * H];    // 32 KB
    for (int idx = threadIdx.x; idx < B * H; idx += 256)
        sctx[idx] = ctx[idx];
    __syncthreads();

    const int warp = threadIdx.x >> 5;
    const int lane = threadIdx.x & 31;
    const int i = blockIdx.x * 8 + warp;

    const float4* wr = reinterpret_cast<const float4*>(W + (size_t)i * H);
    float4 w[8];
#pragma unroll
    for (int k = 0; k < 8; k++)
        w[k] = wr[lane + 32 * k];

#pragma unroll
    for (int b = 0; b < B; b++) {
        const float4* c4 = reinterpret_cast<const float4*>(sctx + b * H);
        float acc = 0.0f;
#pragma unroll
        for (int k = 0; k < 8; k++) {
            const float4 c = c4[lane + 32 * k];
            acc += w[k].x * c.x + w[k].y * c.y + w[k].z * c.z + w[k].w * c.w;
        }
#pragma unroll
        for (int o = 16; o; o >>= 1) acc += __shfl_xor_sync(0xFFFFFFFFu, acc, o);
        if (lane == 0) g_v[b * H + i] = acc;
    }
}

// Kernel 2: 2048 blocks x 256 threads, 16 consecutive rows per block
// (batch-aligned: 256 blocks per batch). Each warp handles 2 rows with all
// 16 LDG.128 front-batched; the v smem stage is issued AFTER the states
// loads so the L2 stage latency hides under the DRAM loads.
__global__ void __launch_bounds__(256, 3) score_kernel(
    const float* __restrict__ states,  // (B, T, H)
    const float* __restrict__ bias,    // (1,)
    float* __restrict__ out)           // (B*T,)
{
    __shared__ float sv[H];            // 4 KB: v for this block's batch

    const int lane = threadIdx.x & 31;
    const int warp = threadIdx.x >> 5;
    const int b    = blockIdx.x >> 8;              // 256 blocks per batch
    const int row0 = blockIdx.x * 16 + warp * 2;   // this warp's first row

    const float4* s0 = reinterpret_cast<const float4*>(states + (size_t)row0 * H);
    const float4* s1 = reinterpret_cast<const float4*>(states + (size_t)(row0 + 1) * H);

    // Front-batch all 16 global loads (DRAM, ~600 cyc)
    float4 x0[8], x1[8];
#pragma unroll
    for (int k = 0; k < 8; k++) x0[k] = s0[lane + 32 * k];
#pragma unroll
    for (int k = 0; k < 8; k++) x1[k] = s1[lane + 32 * k];

    // Stage v (4 KB from L2) — hidden under the states loads above
    reinterpret_cast<float4*>(sv)[threadIdx.x] =
        reinterpret_cast<const float4*>(g_v + b * H)[threadIdx.x];
    __syncthreads();

    float acc0 = 0.0f, acc1 = 0.0f;
#pragma unroll
    for (int k = 0; k < 8; k++) {
        const float4 w = reinterpret_cast<const float4*>(sv)[lane + 32 * k];
        acc0 += x0[k].x * w.x + x0[k].y * w.y + x0[k].z * w.z + x0[k].w * w.w;
        acc1 += x1[k].x * w.x + x1[k].y * w.y + x1[k].z * w.z + x1[k].w * w.w;
    }

#pragma unroll
    for (int o = 16; o; o >>= 1) {
        acc0 += __shfl_xor_sync(0xFFFFFFFFu, acc0, o);
        acc1 += __shfl_xor_sync(0xFFFFFFFFu, acc1, o);
    }

    if (lane == 0) {
        const float bb = bias[0];
        out[row0]     = acc0 + bb;
        out[row0 + 1] = acc1 + bb;
    }
}

extern "C" void kernel_launch(void* const* d_in, const int* in_sizes, int n_in,
                              void* d_out, int out_size)
{
    const float* states = (const float*)d_in[0];   // (B, T, H)
    const float* ctx    = (const float*)d_in[1];   // (B, H)
    const float* W      = (const float*)d_in[2];   // (1, H, H)
    const float* bias   = (const float*)d_in[3];   // (1,)
    float* out = (float*)d_out;                    // (B, T, 1)

    compute_v_kernel<<<H / 8, 256>>>(W, ctx);
    score_kernel<<<(B * T) / 16, 256>>>(states, bias, out);
}

// round 4
// speedup vs baseline: 1.2533x; 1.1302x over previous
#include <cuda_runtime.h>

#define H 1024
#define B 8
#define T 4096

// Scratch: v[b][i] = sum_j W[i][j] * context[b][j]
__device__ float g_v[B * H];

// Kernel 1: one W row per block (1024 blocks x 256 threads).
// Each thread holds one float4 of the W row and dots it against 8 ctx
// float4 loads (ctx = 32 KB, L2-resident after first wave). Warp reduce,
// then cross-warp reduce through 288 B of smem.
__global__ void __launch_bounds__(256) compute_v_kernel(
    const float* __restrict__ W,     // (H, H)
    const float* __restrict__ ctx)   // (B, H)
{
    __shared__ float red[8][9];      // [warp][batch] (+1 pad)

    const int row  = blockIdx.x;
    const int tid  = threadIdx.x;
    const int lane = tid & 31;
    const int warp = tid >> 5;

    const float4 w4 = reinterpret_cast<const float4*>(W + (size_t)row * H)[tid];

    float acc[B];
#pragma unroll
    for (int b = 0; b < B; b++) {
        const float4 c = __ldg(reinterpret_cast<const float4*>(ctx + b * H) + tid);
        acc[b] = w4.x * c.x + w4.y * c.y + w4.z * c.z + w4.w * c.w;
    }

#pragma unroll
    for (int b = 0; b < B; b++) {
#pragma unroll
        for (int o = 16; o; o >>= 1)
            acc[b] += __shfl_xor_sync(0xFFFFFFFFu, acc[b], o);
    }

    if (lane == 0) {
#pragma unroll
        for (int b = 0; b < B; b++) red[warp][b] = acc[b];
    }
    __syncthreads();

    if (tid < B) {
        float s = 0.0f;
#pragma unroll
        for (int w = 0; w < 8; w++) s += red[w][tid];
        g_v[tid * H + row] = s;
    }
}

// Kernel 2: one (b,t) row per warp, 512-thread blocks (16 rows/block),
// 2048 blocks. No shared memory, no __syncthreads: the 8 states LDG.128
// are front-batched (DRAM), and v is pulled via __ldg inside the FMA loop
// (L1/L2-hot, broadcast across warps). Warps are fully independent.
__global__ void __launch_bounds__(512) score_kernel(
    const float* __restrict__ states,  // (B, T, H)
    const float* __restrict__ bias,    // (1,)
    float* __restrict__ out)           // (B*T,)
{
    const int lane = threadIdx.x & 31;
    const int row  = blockIdx.x * 16 + (threadIdx.x >> 5);
    const int b    = row >> 12;        // row / T

    const float4* s4 = reinterpret_cast<const float4*>(states + (size_t)row * H);
    const float4* v4 = reinterpret_cast<const float4*>(g_v + b * H);

    // Front-batch the 8 DRAM loads (one full row = 4 KB per warp)
    float4 x[8];
#pragma unroll
    for (int k = 0; k < 8; k++) x[k] = s4[lane + 32 * k];

    float acc = 0.0f;
#pragma unroll
    for (int k = 0; k < 8; k++) {
        const float4 w = __ldg(v4 + lane + 32 * k);   // L1/L2 hit
        acc += x[k].x * w.x + x[k].y * w.y + x[k].z * w.z + x[k].w * w.w;
    }

#pragma unroll
    for (int o = 16; o; o >>= 1)
        acc += __shfl_xor_sync(0xFFFFFFFFu, acc, o);

    if (lane == 0) out[row] = acc + bias[0];
}

extern "C" void kernel_launch(void* const* d_in, const int* in_sizes, int n_in,
                              void* d_out, int out_size)
{
    const float* states = (const float*)d_in[0];   // (B, T, H)
    const float* ctx    = (const float*)d_in[1];   // (B, H)
    const float* W      = (const float*)d_in[2];   // (1, H, H)
    const float* bias   = (const float*)d_in[3];   // (1,)
    float* out = (float*)d_out;                    // (B, T, 1)

    compute_v_kernel<<<H, 256>>>(W, ctx);
    score_kernel<<<(B * T) / 16, 512>>>(states, bias, out);
}